// round 6
// baseline (speedup 1.0000x reference)
#include <cuda_runtime.h>

#define Bn 256
#define Sn 336
#define Cn 321
#define Hn 512
#define Pn 96
#define NCTA 88

typedef unsigned long long ull;

__device__ float    g_scr[(size_t)Bn * Cn * Hn];
__device__ unsigned g_bar;

__device__ __forceinline__ void fma2(ull &d, ull a, ull b) {
    asm("fma.rn.f32x2 %0, %1, %2, %0;" : "+l"(d) : "l"(a), "l"(b));
}
__device__ __forceinline__ ull dup2(float v) {
    ull r; asm("mov.b64 %0, {%1, %1};" : "=l"(r) : "f"(v)); return r;
}
__device__ __forceinline__ float2 up2(ull v) {
    float2 r; asm("mov.b64 {%0, %1}, %2;" : "=f"(r.x), "=f"(r.y) : "l"(v)); return r;
}
__device__ __forceinline__ float reluN(float x) { return (x < 0.f) ? 0.f : x; }

__global__ void reset_bar_kernel() { g_bar = 0u; }

// ============================================================================
// it_kernel: IT[b,c,h] = bi[h] + sum_s x[b,s,c]*Wi[h,s]   (v4, proven)
// ============================================================================
__global__ void __launch_bounds__(128) it_kernel(
    const float* __restrict__ x, const float* __restrict__ Wi,
    const float* __restrict__ bi)
{
    __shared__ __align__(16) float As[16][68];
    __shared__ __align__(16) float Bs[16][68];
    const int b  = blockIdx.z;
    const int n0 = blockIdx.x * 64;
    const int m0 = blockIdx.y * 64;
    const int t  = threadIdx.x;
    const int tm = t & 15, tn = t >> 4;

    ull acc[4][4];
#pragma unroll
    for (int i = 0; i < 4; i++)
#pragma unroll
        for (int j = 0; j < 4; j++) acc[i][j] = 0ull;

    const float* xb = x + (size_t)b * Sn * Cn;
    const int la_k = t >> 3, la_c = (t & 7) * 8;
    const int lb_n = t & 63, lb_k = (t >> 6) * 8;

    for (int k0 = 0; k0 < Sn; k0 += 16) {
        {
            const float* src = xb + (size_t)(k0 + la_k) * Cn + m0 + la_c;
#pragma unroll
            for (int j = 0; j < 8; j++)
                As[la_k][la_c + j] = (m0 + la_c + j < Cn) ? src[j] : 0.f;
        }
        {
            const float* src = Wi + (size_t)(n0 + lb_n) * Sn + k0 + lb_k;
            float4 v0 = *(const float4*)(src);
            float4 v1 = *(const float4*)(src + 4);
            Bs[lb_k + 0][lb_n] = v0.x; Bs[lb_k + 1][lb_n] = v0.y;
            Bs[lb_k + 2][lb_n] = v0.z; Bs[lb_k + 3][lb_n] = v0.w;
            Bs[lb_k + 4][lb_n] = v1.x; Bs[lb_k + 5][lb_n] = v1.y;
            Bs[lb_k + 6][lb_n] = v1.z; Bs[lb_k + 7][lb_n] = v1.w;
        }
        __syncthreads();
#pragma unroll
        for (int kk = 0; kk < 16; kk++) {
            float4 a = *(const float4*)&As[kk][tm * 4];
            const ull* bp = (const ull*)&Bs[kk][tn * 8];
            ull b0 = bp[0], b1 = bp[1], b2 = bp[2], b3 = bp[3];
            ull a0 = dup2(a.x), a1 = dup2(a.y), a2 = dup2(a.z), a3 = dup2(a.w);
            fma2(acc[0][0], a0, b0); fma2(acc[0][1], a0, b1);
            fma2(acc[0][2], a0, b2); fma2(acc[0][3], a0, b3);
            fma2(acc[1][0], a1, b0); fma2(acc[1][1], a1, b1);
            fma2(acc[1][2], a1, b2); fma2(acc[1][3], a1, b3);
            fma2(acc[2][0], a2, b0); fma2(acc[2][1], a2, b1);
            fma2(acc[2][2], a2, b2); fma2(acc[2][3], a2, b3);
            fma2(acc[3][0], a3, b0); fma2(acc[3][1], a3, b1);
            fma2(acc[3][2], a3, b2); fma2(acc[3][3], a3, b3);
        }
        __syncthreads();
    }
    float biv[8];
#pragma unroll
    for (int j = 0; j < 8; j++) biv[j] = bi[n0 + tn * 8 + j];
#pragma unroll
    for (int i = 0; i < 4; i++) {
        int c = m0 + tm * 4 + i;
        if (c < Cn) {
            float* dst = g_scr + ((size_t)b * Cn + c) * Hn + n0 + tn * 8;
#pragma unroll
            for (int j = 0; j < 4; j++) {
                float2 v = up2(acc[i][j]);
                dst[2 * j]     = v.x + biv[2 * j];
                dst[2 * j + 1] = v.y + biv[2 * j + 1];
            }
        }
    }
}

// ============================================================================
// Persistent recurrence v3: 88 CTAs x 256 threads (2 warps/SMSP).
// CTA tile 32c x 64n. Micro 2c x 4n per thread. NO K-split: every output is
// one sequential fp32 fma chain k=0..511 (chunks ascending, kk ascending) --
// byte-identical accumulation order to the passing v4 kernel.
// smem: Bs[512][64]=128KB resident Wh^T + As[2][64][34]=17.4KB double buffer.
// ============================================================================
__device__ __forceinline__ void gbar(unsigned target) {
    __syncthreads();
    if (threadIdx.x == 0) {
        asm volatile("red.release.gpu.global.add.u32 [%0], 1;"
                     :: "l"(&g_bar) : "memory");
        unsigned v;
        do {
            asm volatile("ld.acquire.gpu.global.u32 %0, [%1];"
                         : "=r"(v) : "l"(&g_bar));
        } while (v < target);
    }
    __syncthreads();
}

extern __shared__ float sm_dyn[];

__global__ void __launch_bounds__(256) rnn_kernel(
    const float* __restrict__ Wh, const float* __restrict__ bh)
{
    float* Bs = sm_dyn;                 // Bs[k*64 + n]
    float* As = sm_dyn + 512 * 64;      // As[buf*64*34 + kk*34 + c]

    const int t   = threadIdx.x;
    const int cta = blockIdx.x;
    const int n0  = (cta & 7) * 64;
    const int m0  = (cta >> 3) * 32;
    const int tm  = t & 15;        // c pair: c = m0 + tm*2 + {0,1}
    const int tn  = t >> 4;        // n quad: n = n0 + tn*4 + {0..3}

    // Wh^T resident: Bs[k][n] = Wh[n0+n][k]   (256 threads, 128 k each)
    {
        const int n = t & 63, kb = (t >> 6) * 128;
        const float* src = Wh + (size_t)(n0 + n) * Hn + kb;
        for (int k = 0; k < 128; k += 4) {
            float4 v = *(const float4*)(src + k);
            Bs[(kb + k + 0) * 64 + n] = v.x; Bs[(kb + k + 1) * 64 + n] = v.y;
            Bs[(kb + k + 2) * 64 + n] = v.z; Bs[(kb + k + 3) * 64 + n] = v.w;
        }
    }
    float bhv[4];
#pragma unroll
    for (int j = 0; j < 4; j++) bhv[j] = bh[n0 + tn * 4 + j];
    __syncthreads();

    // step 0: h0 = reluN(reluN(it+bh)+bh) on own tile (elementwise, 2c x 4n)
#pragma unroll
    for (int i = 0; i < 2; i++) {
        int c = m0 + tm * 2 + i;
        if (c < Cn) {
            float* row = g_scr + (size_t)c * Hn + n0 + tn * 4;
            float4 v = *(const float4*)row;
            float f[4] = { v.x, v.y, v.z, v.w };
#pragma unroll
            for (int j = 0; j < 4; j++) {
                float a = reluN(f[j] + bhv[j]);
                f[j] = reluN(a + bhv[j]);
            }
            *(float4*)row = make_float4(f[0], f[1], f[2], f[3]);
        }
    }
    gbar(NCTA);

    // A-chunk loader: 256 threads, chunk = 64k x 32c. Thread loads 8 k from
    // one c-row (2 x float4), stores transposed into As[k][c].
    const int la_c = t & 31;           // 0..31
    const int la_k = (t >> 5) * 8;     // 0,8,...,56
    const bool cv  = (m0 + la_c) < Cn;

    for (int b = 1; b < Bn; b++) {
        const float* hp   = g_scr + (size_t)(b - 1) * (Cn * Hn);
        const float* arow = hp + (size_t)(m0 + la_c) * Hn + la_k;

        ull acc[2][2];
        acc[0][0] = acc[0][1] = acc[1][0] = acc[1][1] = 0ull;

        float4 p0, p1;
        p0 = cv ? *(const float4*)(arow)     : make_float4(0.f, 0.f, 0.f, 0.f);
        p1 = cv ? *(const float4*)(arow + 4) : make_float4(0.f, 0.f, 0.f, 0.f);
        {
            float* d = As;  // buf 0
            d[(la_k + 0) * 34 + la_c] = p0.x; d[(la_k + 1) * 34 + la_c] = p0.y;
            d[(la_k + 2) * 34 + la_c] = p0.z; d[(la_k + 3) * 34 + la_c] = p0.w;
            d[(la_k + 4) * 34 + la_c] = p1.x; d[(la_k + 5) * 34 + la_c] = p1.y;
            d[(la_k + 6) * 34 + la_c] = p1.z; d[(la_k + 7) * 34 + la_c] = p1.w;
        }
        __syncthreads();

#pragma unroll 1
        for (int ch = 0; ch < 8; ch++) {
            if (ch < 7) {
                const float* s = arow + (ch + 1) * 64;
                p0 = cv ? *(const float4*)(s)     : make_float4(0.f, 0.f, 0.f, 0.f);
                p1 = cv ? *(const float4*)(s + 4) : make_float4(0.f, 0.f, 0.f, 0.f);
            }
            const float* as = As + (ch & 1) * (64 * 34) + tm * 2;
            const float* bs = Bs + (size_t)(ch * 64) * 64 + tn * 4;
#pragma unroll 32
            for (int kk = 0; kk < 64; kk++) {
                float2 a = *(const float2*)(as + kk * 34);
                ulonglong2 bb = *(const ulonglong2*)(bs + kk * 64);
                ull a0 = dup2(a.x), a1 = dup2(a.y);
                fma2(acc[0][0], a0, bb.x); fma2(acc[0][1], a0, bb.y);
                fma2(acc[1][0], a1, bb.x); fma2(acc[1][1], a1, bb.y);
            }
            if (ch < 7) {
                float* d = As + ((ch + 1) & 1) * (64 * 34);
                d[(la_k + 0) * 34 + la_c] = p0.x; d[(la_k + 1) * 34 + la_c] = p0.y;
                d[(la_k + 2) * 34 + la_c] = p0.z; d[(la_k + 3) * 34 + la_c] = p0.w;
                d[(la_k + 4) * 34 + la_c] = p1.x; d[(la_k + 5) * 34 + la_c] = p1.y;
                d[(la_k + 6) * 34 + la_c] = p1.z; d[(la_k + 7) * 34 + la_c] = p1.w;
            }
            __syncthreads();
        }

        // epilogue: h_b = reluN(reluN(it+hh)+hh), in place on g_scr[b]
        float* itrow = g_scr + (size_t)b * (Cn * Hn);
#pragma unroll
        for (int i = 0; i < 2; i++) {
            int c = m0 + tm * 2 + i;
            if (c < Cn) {
                float* row = itrow + (size_t)c * Hn + n0 + tn * 4;
                float4 itv = *(const float4*)row;
                float it[4] = { itv.x, itv.y, itv.z, itv.w };
                float2 v0 = up2(acc[i][0]);
                float2 v1 = up2(acc[i][1]);
                float hh[4] = { v0.x + bhv[0], v0.y + bhv[1],
                                v1.x + bhv[2], v1.y + bhv[3] };
                float f[4];
#pragma unroll
                for (int j = 0; j < 4; j++) {
                    float a = reluN(it[j] + hh[j]);
                    f[j] = reluN(a + hh[j]);
                }
                *(float4*)row = make_float4(f[0], f[1], f[2], f[3]);
            }
        }
        if (b < Bn - 1) gbar((unsigned)(b + 1) * NCTA);
    }
}

// ============================================================================
// final_kernel: out[b,p,c] = (bf[p]+sum_k h[c,k]*Wf[p,k] >= 0) ? 1 : 0 (v4)
// ============================================================================
__global__ void __launch_bounds__(192) final_kernel(
    const float* __restrict__ Wf, const float* __restrict__ bf,
    float* __restrict__ out)
{
    __shared__ __align__(16) float As[16][36];
    __shared__ __align__(16) float Bs[16][100];
    const int b  = blockIdx.y;
    const int m0 = blockIdx.x * 32;
    const int t  = threadIdx.x;
    const int tm = t & 7, tn = t >> 3;

    ull acc[4][2];
#pragma unroll
    for (int i = 0; i < 4; i++) { acc[i][0] = 0ull; acc[i][1] = 0ull; }

    const float* hb = g_scr + (size_t)b * Cn * Hn;
    const int la_c = t >> 2, la_k = (t & 3) * 4;
    const int lb_p = t % 96, lb_k = (t / 96) * 8;

    for (int k0 = 0; k0 < Hn; k0 += 16) {
        if (t < 128) {
            int c = m0 + la_c;
            if (c < Cn) {
                float4 v = *(const float4*)(hb + (size_t)c * Hn + k0 + la_k);
                As[la_k + 0][la_c] = v.x; As[la_k + 1][la_c] = v.y;
                As[la_k + 2][la_c] = v.z; As[la_k + 3][la_c] = v.w;
            } else {
#pragma unroll
                for (int j = 0; j < 4; j++) As[la_k + j][la_c] = 0.f;
            }
        }
        {
            const float* src = Wf + (size_t)lb_p * Hn + k0 + lb_k;
            float4 v0 = *(const float4*)(src);
            float4 v1 = *(const float4*)(src + 4);
            Bs[lb_k + 0][lb_p] = v0.x; Bs[lb_k + 1][lb_p] = v0.y;
            Bs[lb_k + 2][lb_p] = v0.z; Bs[lb_k + 3][lb_p] = v0.w;
            Bs[lb_k + 4][lb_p] = v1.x; Bs[lb_k + 5][lb_p] = v1.y;
            Bs[lb_k + 6][lb_p] = v1.z; Bs[lb_k + 7][lb_p] = v1.w;
        }
        __syncthreads();
#pragma unroll
        for (int kk = 0; kk < 16; kk++) {
            float4 a = *(const float4*)&As[kk][tm * 4];
            ulonglong2 bb = *(const ulonglong2*)&Bs[kk][tn * 4];
            ull a0 = dup2(a.x), a1 = dup2(a.y), a2 = dup2(a.z), a3 = dup2(a.w);
            fma2(acc[0][0], a0, bb.x); fma2(acc[0][1], a0, bb.y);
            fma2(acc[1][0], a1, bb.x); fma2(acc[1][1], a1, bb.y);
            fma2(acc[2][0], a2, bb.x); fma2(acc[2][1], a2, bb.y);
            fma2(acc[3][0], a3, bb.x); fma2(acc[3][1], a3, bb.y);
        }
        __syncthreads();
    }
    float bfv[4];
#pragma unroll
    for (int j = 0; j < 4; j++) bfv[j] = bf[tn * 4 + j];
#pragma unroll
    for (int i = 0; i < 4; i++) {
        int c = m0 + tm * 4 + i;
        if (c < Cn) {
            float2 v0 = up2(acc[i][0]);
            float2 v1 = up2(acc[i][1]);
            float z[4] = { v0.x + bfv[0], v0.y + bfv[1],
                           v1.x + bfv[2], v1.y + bfv[3] };
            size_t base = ((size_t)b * Pn + tn * 4) * Cn + c;
#pragma unroll
            for (int j = 0; j < 4; j++)
                out[base + (size_t)j * Cn] = (z[j] >= 0.f) ? 1.f : 0.f;
        }
    }
}

// ============================================================================
extern "C" void kernel_launch(void* const* d_in, const int* in_sizes, int n_in,
                              void* d_out, int out_size) {
    const float* x  = (const float*)d_in[0];
    const float* Wi = (const float*)d_in[1];
    const float* bi = (const float*)d_in[2];
    const float* Wh = (const float*)d_in[3];
    const float* bh = (const float*)d_in[4];
    const float* Wf = (const float*)d_in[5];
    const float* bf = (const float*)d_in[6];
    float* out = (float*)d_out;

    const int smem = (512 * 64 + 2 * 64 * 34) * 4;  // 148480 B
    cudaFuncSetAttribute(rnn_kernel,
                         cudaFuncAttributeMaxDynamicSharedMemorySize, smem);

    reset_bar_kernel<<<1, 1>>>();
    it_kernel<<<dim3(8, 6, Bn), 128>>>(x, Wi, bi);
    rnn_kernel<<<NCTA, 256, smem>>>(Wh, bh);
    final_kernel<<<dim3(11, Bn), 192>>>(Wf, bf, out);
}

// round 7
// speedup vs baseline: 1.1950x; 1.1950x over previous
#include <cuda_runtime.h>

#define Bn 256
#define Sn 336
#define Cn 321
#define Hn 512
#define Pn 96
#define NCTA 88

typedef unsigned long long ull;

__device__ float g_scr[(size_t)Bn * Cn * Hn];

__device__ __forceinline__ void fma2(ull &d, ull a, ull b) {
    asm("fma.rn.f32x2 %0, %1, %2, %0;" : "+l"(d) : "l"(a), "l"(b));
}
__device__ __forceinline__ ull dup2(float v) {
    ull r; asm("mov.b64 %0, {%1, %1};" : "=l"(r) : "f"(v)); return r;
}
__device__ __forceinline__ float2 up2(ull v) {
    float2 r; asm("mov.b64 {%0, %1}, %2;" : "=f"(r.x), "=f"(r.y) : "l"(v)); return r;
}
__device__ __forceinline__ float reluN(float x) { return (x < 0.f) ? 0.f : x; }
__device__ __forceinline__ void cluster_sync() {
    asm volatile("barrier.cluster.arrive.aligned;" ::: "memory");
    asm volatile("barrier.cluster.wait.aligned;" ::: "memory");
}

// ============================================================================
// it_kernel: IT[b,c,h] = bi[h] + sum_s x[b,s,c]*Wi[h,s]   (v1, proven)
// ============================================================================
__global__ void __launch_bounds__(128) it_kernel(
    const float* __restrict__ x, const float* __restrict__ Wi,
    const float* __restrict__ bi)
{
    __shared__ __align__(16) float As[16][68];
    __shared__ __align__(16) float Bs[16][68];
    const int b  = blockIdx.z;
    const int n0 = blockIdx.x * 64;
    const int m0 = blockIdx.y * 64;
    const int t  = threadIdx.x;
    const int tm = t & 15, tn = t >> 4;

    ull acc[4][4];
#pragma unroll
    for (int i = 0; i < 4; i++)
#pragma unroll
        for (int j = 0; j < 4; j++) acc[i][j] = 0ull;

    const float* xb = x + (size_t)b * Sn * Cn;
    const int la_k = t >> 3, la_c = (t & 7) * 8;
    const int lb_n = t & 63, lb_k = (t >> 6) * 8;

    for (int k0 = 0; k0 < Sn; k0 += 16) {
        {
            const float* src = xb + (size_t)(k0 + la_k) * Cn + m0 + la_c;
#pragma unroll
            for (int j = 0; j < 8; j++)
                As[la_k][la_c + j] = (m0 + la_c + j < Cn) ? src[j] : 0.f;
        }
        {
            const float* src = Wi + (size_t)(n0 + lb_n) * Sn + k0 + lb_k;
            float4 v0 = *(const float4*)(src);
            float4 v1 = *(const float4*)(src + 4);
            Bs[lb_k + 0][lb_n] = v0.x; Bs[lb_k + 1][lb_n] = v0.y;
            Bs[lb_k + 2][lb_n] = v0.z; Bs[lb_k + 3][lb_n] = v0.w;
            Bs[lb_k + 4][lb_n] = v1.x; Bs[lb_k + 5][lb_n] = v1.y;
            Bs[lb_k + 6][lb_n] = v1.z; Bs[lb_k + 7][lb_n] = v1.w;
        }
        __syncthreads();
#pragma unroll
        for (int kk = 0; kk < 16; kk++) {
            float4 a = *(const float4*)&As[kk][tm * 4];
            const ull* bp = (const ull*)&Bs[kk][tn * 8];
            ull b0 = bp[0], b1 = bp[1], b2 = bp[2], b3 = bp[3];
            ull a0 = dup2(a.x), a1 = dup2(a.y), a2 = dup2(a.z), a3 = dup2(a.w);
            fma2(acc[0][0], a0, b0); fma2(acc[0][1], a0, b1);
            fma2(acc[0][2], a0, b2); fma2(acc[0][3], a0, b3);
            fma2(acc[1][0], a1, b0); fma2(acc[1][1], a1, b1);
            fma2(acc[1][2], a1, b2); fma2(acc[1][3], a1, b3);
            fma2(acc[2][0], a2, b0); fma2(acc[2][1], a2, b1);
            fma2(acc[2][2], a2, b2); fma2(acc[2][3], a2, b3);
            fma2(acc[3][0], a3, b0); fma2(acc[3][1], a3, b1);
            fma2(acc[3][2], a3, b2); fma2(acc[3][3], a3, b3);
        }
        __syncthreads();
    }
    float biv[8];
#pragma unroll
    for (int j = 0; j < 8; j++) biv[j] = bi[n0 + tn * 8 + j];
#pragma unroll
    for (int i = 0; i < 4; i++) {
        int c = m0 + tm * 4 + i;
        if (c < Cn) {
            float* dst = g_scr + ((size_t)b * Cn + c) * Hn + n0 + tn * 8;
#pragma unroll
            for (int j = 0; j < 4; j++) {
                float2 v = up2(acc[i][j]);
                dst[2 * j]     = v.x + biv[2 * j];
                dst[2 * j + 1] = v.y + biv[2 * j + 1];
            }
        }
    }
}

// ============================================================================
// Persistent recurrence v4: 88 CTAs = 11 clusters x 8. Cluster q owns c-rows
// [32q, 32q+32); its 8 CTAs own n-tiles of 64. Only intra-cluster sync needed
// (c-rows evolve independently). Microkernel = proven v4 4c x 4n, k chain
// ascending 0..511 (4 chunks of 128) -> bit-identical trajectory.
// smem: Bs[512][64]=128KB Wh^T resident + As[2][128][36]=36KB double buffer.
// ============================================================================
extern __shared__ float sm_dyn[];

__global__ void __cluster_dims__(8, 1, 1) __launch_bounds__(128) rnn_kernel(
    const float* __restrict__ Wh, const float* __restrict__ bh)
{
    float* Bs = sm_dyn;                 // Bs[k*64 + n]
    float* As = sm_dyn + 512 * 64;      // As[buf*128*36 + kk*36 + c]

    const int t   = threadIdx.x;
    const int cta = blockIdx.x;
    const int n0  = (cta & 7) * 64;
    const int m0  = (cta >> 3) * 32;
    const int tm  = t & 7;         // c quad: c = m0 + tm*4 + i
    const int tn  = t >> 3;        // n quad: n = n0 + tn*4 + j

    // Wh^T resident: Bs[k][n] = Wh[n0+n][k]
    {
        const int n = t & 63, kb = (t >> 6) * 256;
        const float* src = Wh + (size_t)(n0 + n) * Hn + kb;
        for (int k = 0; k < 256; k += 4) {
            float4 v = *(const float4*)(src + k);
            Bs[(kb + k + 0) * 64 + n] = v.x; Bs[(kb + k + 1) * 64 + n] = v.y;
            Bs[(kb + k + 2) * 64 + n] = v.z; Bs[(kb + k + 3) * 64 + n] = v.w;
        }
    }
    float bhv[4];
#pragma unroll
    for (int j = 0; j < 4; j++) bhv[j] = bh[n0 + tn * 4 + j];
    __syncthreads();

    // step 0: h0 = reluN(reluN(it+bh)+bh) on own tile
#pragma unroll
    for (int i = 0; i < 4; i++) {
        int c = m0 + tm * 4 + i;
        if (c < Cn) {
            float* row = g_scr + (size_t)c * Hn + n0 + tn * 4;
            float4 v = *(const float4*)row;
            float f[4] = { v.x, v.y, v.z, v.w };
#pragma unroll
            for (int j = 0; j < 4; j++) {
                float a = reluN(f[j] + bhv[j]);
                f[j] = reluN(a + bhv[j]);
            }
            *(float4*)row = make_float4(f[0], f[1], f[2], f[3]);
        }
    }
    cluster_sync();

    // A staging: lane la_c = t&31 owns c-row m0+la_c; warp w = t>>5 owns
    // k-window [w*32, w*32+32) of each 128-k chunk (1 L1 line per row/chunk).
    // Stores As[kk][la_c]: lanes hit 32 distinct banks -> conflict-free.
    const int la_c = t & 31;
    const int la_kb = (t >> 5) * 32;
    const bool cv = (m0 + la_c) < Cn;

    for (int b = 1; b < Bn; b++) {
        const float* arow = g_scr + (size_t)(b - 1) * (Cn * Hn)
                          + (size_t)(m0 + la_c) * Hn + la_kb;
        float* itrow = g_scr + (size_t)b * (Cn * Hn);

        ull acc[4][2];
#pragma unroll
        for (int i = 0; i < 4; i++) { acc[i][0] = 0ull; acc[i][1] = 0ull; }

        // prefetch IT tile (hides L2 latency behind the chunk loop)
        float4 itv[4];
#pragma unroll
        for (int i = 0; i < 4; i++) {
            int c = m0 + tm * 4 + i;
            itv[i] = (c < Cn) ? *(const float4*)(itrow + (size_t)c * Hn + n0 + tn * 4)
                              : make_float4(0.f, 0.f, 0.f, 0.f);
        }

        float4 pre[8];
#pragma unroll
        for (int q = 0; q < 8; q++)
            pre[q] = cv ? *(const float4*)(arow + q * 4)
                        : make_float4(0.f, 0.f, 0.f, 0.f);
        {
            float* d = As;
#pragma unroll
            for (int q = 0; q < 8; q++) {
                int kr = la_kb + q * 4;
                d[(kr + 0) * 36 + la_c] = pre[q].x;
                d[(kr + 1) * 36 + la_c] = pre[q].y;
                d[(kr + 2) * 36 + la_c] = pre[q].z;
                d[(kr + 3) * 36 + la_c] = pre[q].w;
            }
        }
        __syncthreads();

#pragma unroll 1
        for (int ch = 0; ch < 4; ch++) {
            if (ch < 3) {
                const float* s = arow + (ch + 1) * 128;
#pragma unroll
                for (int q = 0; q < 8; q++)
                    pre[q] = cv ? *(const float4*)(s + q * 4)
                                : make_float4(0.f, 0.f, 0.f, 0.f);
            }
            const float* as = As + (ch & 1) * (128 * 36) + tm * 4;
            const float* bs = Bs + (size_t)(ch * 128) * 64 + tn * 4;
#pragma unroll 16
            for (int kk = 0; kk < 128; kk++) {
                float4 a = *(const float4*)(as + kk * 36);
                ulonglong2 bb = *(const ulonglong2*)(bs + kk * 64);
                ull a0 = dup2(a.x), a1 = dup2(a.y),
                    a2 = dup2(a.z), a3 = dup2(a.w);
                fma2(acc[0][0], a0, bb.x); fma2(acc[0][1], a0, bb.y);
                fma2(acc[1][0], a1, bb.x); fma2(acc[1][1], a1, bb.y);
                fma2(acc[2][0], a2, bb.x); fma2(acc[2][1], a2, bb.y);
                fma2(acc[3][0], a3, bb.x); fma2(acc[3][1], a3, bb.y);
            }
            if (ch < 3) {
                float* d = As + ((ch + 1) & 1) * (128 * 36);
#pragma unroll
                for (int q = 0; q < 8; q++) {
                    int kr = la_kb + q * 4;
                    d[(kr + 0) * 36 + la_c] = pre[q].x;
                    d[(kr + 1) * 36 + la_c] = pre[q].y;
                    d[(kr + 2) * 36 + la_c] = pre[q].z;
                    d[(kr + 3) * 36 + la_c] = pre[q].w;
                }
            }
            __syncthreads();
        }

        // epilogue: h_b = reluN(reluN(it+hh)+hh), in place on g_scr[b]
#pragma unroll
        for (int i = 0; i < 4; i++) {
            int c = m0 + tm * 4 + i;
            if (c < Cn) {
                float* row = itrow + (size_t)c * Hn + n0 + tn * 4;
                float it[4] = { itv[i].x, itv[i].y, itv[i].z, itv[i].w };
                float2 v0 = up2(acc[i][0]);
                float2 v1 = up2(acc[i][1]);
                float hh[4] = { v0.x + bhv[0], v0.y + bhv[1],
                                v1.x + bhv[2], v1.y + bhv[3] };
                float f[4];
#pragma unroll
                for (int j = 0; j < 4; j++) {
                    float a = reluN(it[j] + hh[j]);
                    f[j] = reluN(a + hh[j]);
                }
                *(float4*)row = make_float4(f[0], f[1], f[2], f[3]);
            }
        }
        if (b < Bn - 1) cluster_sync();
    }
}

// ============================================================================
// final_kernel v2: tile 64c x 96p, 192 threads, micro 4c x 8p (fma-bound).
// Per-output k chain = ascending 0..511, bias at end -> bit-identical to v1.
// ============================================================================
__global__ void __launch_bounds__(192) final_kernel(
    const float* __restrict__ Wf, const float* __restrict__ bf,
    float* __restrict__ out)
{
    __shared__ __align__(16) float As[16][68];    // [kk][c] 64 + pad
    __shared__ __align__(16) float Bs[16][100];   // [kk][p] 96 + pad
    const int b  = blockIdx.y;
    const int m0 = blockIdx.x * 64;
    const int t  = threadIdx.x;
    const int tm = t & 15;     // 16 x 4c = 64
    const int tn = t >> 4;     // 12 x 8p = 96

    ull acc[4][4];
#pragma unroll
    for (int i = 0; i < 4; i++)
#pragma unroll
        for (int j = 0; j < 4; j++) acc[i][j] = 0ull;

    const float* hb = g_scr + (size_t)b * Cn * Hn;
    const int la_c = t >> 1, la_k = (t & 1) * 8;   // t<128: 64c x 16k
    const int lb_p = t % 96,  lb_k = (t / 96) * 8;

    for (int k0 = 0; k0 < Hn; k0 += 16) {
        if (t < 128) {
            int c = m0 + la_c;
            if (c < Cn) {
                const float* src = hb + (size_t)c * Hn + k0 + la_k;
                float4 v0 = *(const float4*)(src);
                float4 v1 = *(const float4*)(src + 4);
                As[la_k + 0][la_c] = v0.x; As[la_k + 1][la_c] = v0.y;
                As[la_k + 2][la_c] = v0.z; As[la_k + 3][la_c] = v0.w;
                As[la_k + 4][la_c] = v1.x; As[la_k + 5][la_c] = v1.y;
                As[la_k + 6][la_c] = v1.z; As[la_k + 7][la_c] = v1.w;
            } else {
#pragma unroll
                for (int j = 0; j < 8; j++) As[la_k + j][la_c] = 0.f;
            }
        }
        {
            const float* src = Wf + (size_t)lb_p * Hn + k0 + lb_k;
            float4 v0 = *(const float4*)(src);
            float4 v1 = *(const float4*)(src + 4);
            Bs[lb_k + 0][lb_p] = v0.x; Bs[lb_k + 1][lb_p] = v0.y;
            Bs[lb_k + 2][lb_p] = v0.z; Bs[lb_k + 3][lb_p] = v0.w;
            Bs[lb_k + 4][lb_p] = v1.x; Bs[lb_k + 5][lb_p] = v1.y;
            Bs[lb_k + 6][lb_p] = v1.z; Bs[lb_k + 7][lb_p] = v1.w;
        }
        __syncthreads();
#pragma unroll
        for (int kk = 0; kk < 16; kk++) {
            float4 a = *(const float4*)&As[kk][tm * 4];
            ulonglong2 b01 = *(const ulonglong2*)&Bs[kk][tn * 8];
            ulonglong2 b23 = *(const ulonglong2*)&Bs[kk][tn * 8 + 4];
            ull a0 = dup2(a.x), a1 = dup2(a.y), a2 = dup2(a.z), a3 = dup2(a.w);
            fma2(acc[0][0], a0, b01.x); fma2(acc[0][1], a0, b01.y);
            fma2(acc[0][2], a0, b23.x); fma2(acc[0][3], a0, b23.y);
            fma2(acc[1][0], a1, b01.x); fma2(acc[1][1], a1, b01.y);
            fma2(acc[1][2], a1, b23.x); fma2(acc[1][3], a1, b23.y);
            fma2(acc[2][0], a2, b01.x); fma2(acc[2][1], a2, b01.y);
            fma2(acc[2][2], a2, b23.x); fma2(acc[2][3], a2, b23.y);
            fma2(acc[3][0], a3, b01.x); fma2(acc[3][1], a3, b01.y);
            fma2(acc[3][2], a3, b23.x); fma2(acc[3][3], a3, b23.y);
        }
        __syncthreads();
    }
    float bfv[8];
#pragma unroll
    for (int j = 0; j < 8; j++) bfv[j] = bf[tn * 8 + j];
#pragma unroll
    for (int i = 0; i < 4; i++) {
        int c = m0 + tm * 4 + i;
        if (c < Cn) {
            size_t base = ((size_t)b * Pn + tn * 8) * Cn + c;
#pragma unroll
            for (int j = 0; j < 4; j++) {
                float2 v = up2(acc[i][j]);
                float z0 = v.x + bfv[2 * j];
                float z1 = v.y + bfv[2 * j + 1];
                out[base + (size_t)(2 * j) * Cn]     = (z0 >= 0.f) ? 1.f : 0.f;
                out[base + (size_t)(2 * j + 1) * Cn] = (z1 >= 0.f) ? 1.f : 0.f;
            }
        }
    }
}

// ============================================================================
extern "C" void kernel_launch(void* const* d_in, const int* in_sizes, int n_in,
                              void* d_out, int out_size) {
    const float* x  = (const float*)d_in[0];
    const float* Wi = (const float*)d_in[1];
    const float* bi = (const float*)d_in[2];
    const float* Wh = (const float*)d_in[3];
    const float* bh = (const float*)d_in[4];
    const float* Wf = (const float*)d_in[5];
    const float* bf = (const float*)d_in[6];
    float* out = (float*)d_out;

    const int smem = (512 * 64 + 2 * 128 * 36) * 4;  // 167936 B
    cudaFuncSetAttribute(rnn_kernel,
                         cudaFuncAttributeMaxDynamicSharedMemorySize, smem);

    it_kernel<<<dim3(8, 6, Bn), 128>>>(x, Wi, bi);
    rnn_kernel<<<NCTA, 128, smem>>>(Wh, bh);
    final_kernel<<<dim3(6, Bn), 192>>>(Wf, bf, out);
}